// round 2
// baseline (speedup 1.0000x reference)
#include <cuda_runtime.h>
#include <cuda_bf16.h>

#define NN 100000
#define HC 128          // H*C
#define FULL 0xffffffffu
#define CSR_CAP 1900000

// ---------------- scratch (static __device__, no allocs) ----------------
__device__ float g_h[NN * HC];       // transformed features per layer [N,H,C]
__device__ float g_s[NN * 4];        // src attention coeff per node/head
__device__ float g_d[NN * 4];        // dst attention coeff per node/head
__device__ float g_f1[NN * 32];      // layer-1 output
__device__ float g_f2[NN * 32];      // layer-2 output
__device__ int   g_deg[NN];
__device__ int   g_start[NN + 1];
__device__ int   g_cursor[NN];
__device__ int   g_csr[CSR_CAP];     // src index per (dst-sorted) edge

// ---------------- CSR build ----------------
__global__ void k_init_deg() {
    int i = blockIdx.x * blockDim.x + threadIdx.x;
    if (i < NN) g_deg[i] = 1;   // self loop
}

__global__ void k_hist(const int* __restrict__ dst, int E) {
    int i = blockIdx.x * blockDim.x + threadIdx.x;
    if (i < E) atomicAdd(&g_deg[dst[i]], 1);
}

// single-block exclusive scan of g_deg -> g_start (warp-shuffle based)
__global__ void k_scan(int n) {
    __shared__ int wsum[32];
    __shared__ int carry;
    int t = threadIdx.x, lane = t & 31, wid = t >> 5;
    if (t == 0) carry = 0;
    __syncthreads();
    int chunks = (n + 1023) / 1024;
    for (int ch = 0; ch < chunks; ch++) {
        int i = ch * 1024 + t;
        int v = (i < n) ? g_deg[i] : 0;
        int incl = v;
        #pragma unroll
        for (int off = 1; off < 32; off <<= 1) {
            int u = __shfl_up_sync(FULL, incl, off);
            if (lane >= off) incl += u;
        }
        if (lane == 31) wsum[wid] = incl;
        __syncthreads();
        if (wid == 0) {
            int wv = wsum[lane];
            int wincl = wv;
            #pragma unroll
            for (int off = 1; off < 32; off <<= 1) {
                int u = __shfl_up_sync(FULL, wincl, off);
                if (lane >= off) wincl += u;
            }
            wsum[lane] = wincl - wv;   // exclusive warp offsets
        }
        __syncthreads();
        int excl = carry + wsum[wid] + incl - v;
        if (i < n) g_start[i] = excl;
        __syncthreads();
        if (t == 1023) carry = excl + v;
        __syncthreads();
    }
    if (t == 0) g_start[n] = carry;
}

__global__ void k_selfloop() {
    int i = blockIdx.x * blockDim.x + threadIdx.x;
    if (i < NN) {
        g_cursor[i] = 1;
        int p = g_start[i];
        if (p < CSR_CAP) g_csr[p] = i;
    }
}

__global__ void k_scatter(const int* __restrict__ src, const int* __restrict__ dst, int E) {
    int i = blockIdx.x * blockDim.x + threadIdx.x;
    if (i < E) {
        int d = dst[i];
        int pos = g_start[d] + atomicAdd(&g_cursor[d], 1);
        if (pos < CSR_CAP) g_csr[pos] = src[i];
    }
}

// ---------------- per-layer transform: h = feat @ W, s/d attention coeffs ----------------
// LAYER=1: feat comes from param pointer (x). LAYER=2: feat = g_f1.
// Writes g_h, g_s, g_d directly.
template <int K, int LAYER>
__global__ void k_transform(const float* __restrict__ feat_in,
                            const float* __restrict__ W,
                            const float* __restrict__ asrc,
                            const float* __restrict__ adst) {
    const int NPB = 8;
    __shared__ float sW[K * 128];
    __shared__ float sA[256];
    __shared__ float sF[NPB * K];
    const float* feat = (LAYER == 1) ? feat_in : g_f1;
    int t = threadIdx.x;  // 128 threads
    for (int i = t; i < K * 128; i += 128) sW[i] = W[i];
    sA[t]       = asrc[t];
    sA[128 + t] = adst[t];
    int nbase = blockIdx.x * NPB;
    for (int i = t; i < NPB * K; i += 128) {
        long idx = (long)nbase * K + i;
        sF[i] = (idx < (long)NN * K) ? feat[idx] : 0.f;
    }
    __syncthreads();
    int lane = t & 31, hd = t >> 5;
    #pragma unroll
    for (int j = 0; j < NPB; j++) {
        int n = nbase + j;
        if (n >= NN) break;
        float acc = 0.f;
        #pragma unroll
        for (int k = 0; k < K; k++) acc = fmaf(sF[j * K + k], sW[k * 128 + t], acc);
        g_h[n * 128 + t] = acc;
        float sv = acc * sA[t];
        float dv = acc * sA[128 + t];
        #pragma unroll
        for (int off = 16; off; off >>= 1) {
            sv += __shfl_xor_sync(FULL, sv, off);
            dv += __shfl_xor_sync(FULL, dv, off);
        }
        if (lane == 0) { g_s[n * 4 + hd] = sv; g_d[n * 4 + hd] = dv; }
    }
}

// ---------------- aggregation: segment softmax + weighted sum, mean heads, +b, relu ----------------
// LAYER=1 writes g_f1, LAYER=2 writes g_f2.
template <int LAYER>
__global__ void k_aggregate(const float* __restrict__ bias) {
    int n = blockIdx.x * (blockDim.x >> 5) + (threadIdx.x >> 5);
    if (n >= NN) return;
    int lane = threadIdx.x & 31;
    int e0 = g_start[n], e1 = g_start[n + 1];
    float d0 = g_d[n * 4 + 0], d1 = g_d[n * 4 + 1];
    float d2 = g_d[n * 4 + 2], d3 = g_d[n * 4 + 3];

    // pass A: per-head max (lane-parallel over edges)
    float m0 = -1e30f, m1 = -1e30f, m2 = -1e30f, m3 = -1e30f;
    for (int e = e0 + lane; e < e1; e += 32) {
        int s = g_csr[e];
        const float* sp = g_s + s * 4;
        float a0 = sp[0] + d0; a0 = a0 > 0.f ? a0 : 0.2f * a0; m0 = fmaxf(m0, a0);
        float a1 = sp[1] + d1; a1 = a1 > 0.f ? a1 : 0.2f * a1; m1 = fmaxf(m1, a1);
        float a2 = sp[2] + d2; a2 = a2 > 0.f ? a2 : 0.2f * a2; m2 = fmaxf(m2, a2);
        float a3 = sp[3] + d3; a3 = a3 > 0.f ? a3 : 0.2f * a3; m3 = fmaxf(m3, a3);
    }
    #pragma unroll
    for (int off = 16; off; off >>= 1) {
        m0 = fmaxf(m0, __shfl_xor_sync(FULL, m0, off));
        m1 = fmaxf(m1, __shfl_xor_sync(FULL, m1, off));
        m2 = fmaxf(m2, __shfl_xor_sync(FULL, m2, off));
        m3 = fmaxf(m3, __shfl_xor_sync(FULL, m3, off));
    }

    // pass B: softmax-weighted accumulation; lane = channel
    float acc0 = 0.f, acc1 = 0.f, acc2 = 0.f, acc3 = 0.f;
    float den0 = 0.f, den1 = 0.f, den2 = 0.f, den3 = 0.f;
    for (int e = e0; e < e1; e++) {
        int s = g_csr[e];  // warp-uniform
        const float* sp = g_s + s * 4;
        float a0 = sp[0] + d0; a0 = a0 > 0.f ? a0 : 0.2f * a0; float w0 = __expf(a0 - m0); den0 += w0;
        float a1 = sp[1] + d1; a1 = a1 > 0.f ? a1 : 0.2f * a1; float w1 = __expf(a1 - m1); den1 += w1;
        float a2 = sp[2] + d2; a2 = a2 > 0.f ? a2 : 0.2f * a2; float w2 = __expf(a2 - m2); den2 += w2;
        float a3 = sp[3] + d3; a3 = a3 > 0.f ? a3 : 0.2f * a3; float w3 = __expf(a3 - m3); den3 += w3;
        const float* hp = g_h + s * 128 + lane;
        acc0 = fmaf(w0, hp[0],  acc0);
        acc1 = fmaf(w1, hp[32], acc1);
        acc2 = fmaf(w2, hp[64], acc2);
        acc3 = fmaf(w3, hp[96], acc3);
    }
    float o = acc0 / den0 + acc1 / den1 + acc2 / den2 + acc3 / den3;
    o = 0.25f * o + bias[lane];
    float r = fmaxf(o, 0.f);
    if (LAYER == 1) g_f1[n * 32 + lane] = r;
    else            g_f2[n * 32 + lane] = r;
}

// ---------------- node logits ----------------
__global__ void k_node_logits(const float* __restrict__ Wn,
                              const float* __restrict__ bn,
                              float* __restrict__ out) {
    int n = blockIdx.x * blockDim.x + threadIdx.x;
    if (n >= NN) return;
    float o0 = bn[0], o1 = bn[1];
    const float4* fp = (const float4*)(g_f2 + n * 32);
    #pragma unroll
    for (int q = 0; q < 8; q++) {
        float4 v = fp[q];
        int k = q * 4;
        o0 = fmaf(v.x, __ldg(&Wn[k * 2]),       o0);
        o1 = fmaf(v.x, __ldg(&Wn[k * 2 + 1]),   o1);
        o0 = fmaf(v.y, __ldg(&Wn[(k+1) * 2]),   o0);
        o1 = fmaf(v.y, __ldg(&Wn[(k+1) * 2+1]), o1);
        o0 = fmaf(v.z, __ldg(&Wn[(k+2) * 2]),   o0);
        o1 = fmaf(v.z, __ldg(&Wn[(k+2) * 2+1]), o1);
        o0 = fmaf(v.w, __ldg(&Wn[(k+3) * 2]),   o0);
        o1 = fmaf(v.w, __ldg(&Wn[(k+3) * 2+1]), o1);
    }
    out[n * 2]     = o0;
    out[n * 2 + 1] = o1;
}

// ---------------- edge MLP: relu(cat(h[a],h[b]) @ We1 + be1) @ We2 + be2 ----------------
__global__ void k_edge_mlp(const int* __restrict__ ea,
                           const int* __restrict__ eb, int EL,
                           const float* __restrict__ We1,
                           const float* __restrict__ be1,
                           const float* __restrict__ We2,
                           const float* __restrict__ be2,
                           float* __restrict__ out) {
    __shared__ float sW[64 * 64];
    __shared__ float sB[64];
    __shared__ float sV[64];
    __shared__ float sb2;
    int t = threadIdx.x;  // 256
    for (int i = t; i < 4096; i += 256) sW[i] = We1[i];
    if (t < 64) { sB[t] = be1[t]; sV[t] = We2[t]; }
    if (t == 0) sb2 = be2[0];
    __syncthreads();
    int lane = t & 31;
    int e = blockIdx.x * 8 + (t >> 5);
    if (e >= EL) return;
    int a = ea[e], b = eb[e];
    float ei0 = g_f2[a * 32 + lane];
    float ei1 = g_f2[b * 32 + lane];
    float h0 = sB[lane], h1 = sB[lane + 32];
    #pragma unroll
    for (int j = 0; j < 32; j++) {
        float v = __shfl_sync(FULL, ei0, j);
        h0 = fmaf(v, sW[j * 64 + lane],      h0);
        h1 = fmaf(v, sW[j * 64 + lane + 32], h1);
    }
    #pragma unroll
    for (int j = 0; j < 32; j++) {
        float v = __shfl_sync(FULL, ei1, j);
        h0 = fmaf(v, sW[(j + 32) * 64 + lane],      h0);
        h1 = fmaf(v, sW[(j + 32) * 64 + lane + 32], h1);
    }
    h0 = fmaxf(h0, 0.f);
    h1 = fmaxf(h1, 0.f);
    float p = h0 * sV[lane] + h1 * sV[lane + 32];
    #pragma unroll
    for (int off = 16; off; off >>= 1) p += __shfl_xor_sync(FULL, p, off);
    if (lane == 0) out[e] = p + sb2;
}

// ---------------- launch: ONLY kernel launches, nothing else ----------------
extern "C" void kernel_launch(void* const* d_in, const int* in_sizes, int n_in,
                              void* d_out, int out_size) {
    const float* x    = (const float*)d_in[0];
    const int*   ei   = (const int*)d_in[1];
    const int*   eli  = (const int*)d_in[2];
    const float* W1   = (const float*)d_in[3];
    const float* as1  = (const float*)d_in[4];
    const float* ad1  = (const float*)d_in[5];
    const float* b1   = (const float*)d_in[6];
    const float* W2   = (const float*)d_in[7];
    const float* as2  = (const float*)d_in[8];
    const float* ad2  = (const float*)d_in[9];
    const float* b2   = (const float*)d_in[10];
    const float* Wn   = (const float*)d_in[11];
    const float* bn   = (const float*)d_in[12];
    const float* We1  = (const float*)d_in[13];
    const float* be1  = (const float*)d_in[14];
    const float* We2  = (const float*)d_in[15];
    const float* be2  = (const float*)d_in[16];
    float* out = (float*)d_out;

    int E  = in_sizes[1] / 2;
    int EL = in_sizes[2] / 2;
    const int* src  = ei;
    const int* dst  = ei + E;
    const int* ea   = eli;
    const int* eb   = eli + EL;

    // CSR build
    k_init_deg<<<(NN + 255) / 256, 256>>>();
    k_hist<<<(E + 255) / 256, 256>>>(dst, E);
    k_scan<<<1, 1024>>>(NN);
    k_selfloop<<<(NN + 255) / 256, 256>>>();
    k_scatter<<<(E + 255) / 256, 256>>>(src, dst, E);

    const int TGRID = (NN + 7) / 8;   // 8 nodes per block
    const int AGRID = (NN + 7) / 8;   // 8 warps per block, 1 node per warp

    // layer 1
    k_transform<9, 1><<<TGRID, 128>>>(x, W1, as1, ad1);
    k_aggregate<1><<<AGRID, 256>>>(b1);
    // layer 2
    k_transform<32, 2><<<TGRID, 128>>>(nullptr, W2, as2, ad2);
    k_aggregate<2><<<AGRID, 256>>>(b2);

    // heads
    k_node_logits<<<(NN + 255) / 256, 256>>>(Wn, bn, out);
    k_edge_mlp<<<(EL + 7) / 8, 256>>>(ea, eb, EL, We1, be1, We2, be2, out + NN * 2);
}

// round 4
// speedup vs baseline: 1.2113x; 1.2113x over previous
#include <cuda_runtime.h>
#include <cuda_bf16.h>

#define NN 100000
#define HC 128          // H*C
#define FULL 0xffffffffu
#define CSR_CAP 1900000

// ---------------- scratch (static __device__, no allocs) ----------------
__device__ float g_h[NN * HC];       // transformed features per layer [N,H,C]
__device__ float g_s[NN * 4];        // src attention coeff per node/head
__device__ float g_d[NN * 4];        // dst attention coeff per node/head
__device__ float g_f1[NN * 32];      // layer-1 output
__device__ float g_f2[NN * 32];      // layer-2 output
__device__ int   g_deg[NN];
__device__ int   g_start[NN + 1];
__device__ int   g_cursor[NN];
__device__ int   g_csr[CSR_CAP];     // src index per (dst-sorted) edge

// ---------------- CSR build ----------------
__global__ void k_init_deg() {
    int i = blockIdx.x * blockDim.x + threadIdx.x;
    if (i < NN) g_deg[i] = 1;   // self loop
}

__global__ void k_hist(const int* __restrict__ dst, int E) {
    int i = blockIdx.x * blockDim.x + threadIdx.x;
    if (i < E) atomicAdd(&g_deg[dst[i]], 1);
}

// single-block exclusive scan of g_deg -> g_start (warp-shuffle based)
__global__ void k_scan(int n) {
    __shared__ int wsum[32];
    __shared__ int carry;
    int t = threadIdx.x, lane = t & 31, wid = t >> 5;
    if (t == 0) carry = 0;
    __syncthreads();
    int chunks = (n + 1023) / 1024;
    for (int ch = 0; ch < chunks; ch++) {
        int i = ch * 1024 + t;
        int v = (i < n) ? g_deg[i] : 0;
        int incl = v;
        #pragma unroll
        for (int off = 1; off < 32; off <<= 1) {
            int u = __shfl_up_sync(FULL, incl, off);
            if (lane >= off) incl += u;
        }
        if (lane == 31) wsum[wid] = incl;
        __syncthreads();
        if (wid == 0) {
            int wv = wsum[lane];
            int wincl = wv;
            #pragma unroll
            for (int off = 1; off < 32; off <<= 1) {
                int u = __shfl_up_sync(FULL, wincl, off);
                if (lane >= off) wincl += u;
            }
            wsum[lane] = wincl - wv;   // exclusive warp offsets
        }
        __syncthreads();
        int excl = carry + wsum[wid] + incl - v;
        if (i < n) g_start[i] = excl;
        __syncthreads();
        if (t == 1023) carry = excl + v;
        __syncthreads();
    }
    if (t == 0) g_start[n] = carry;
}

__global__ void k_selfloop() {
    int i = blockIdx.x * blockDim.x + threadIdx.x;
    if (i < NN) {
        g_cursor[i] = 1;
        int p = g_start[i];
        if (p < CSR_CAP) g_csr[p] = i;
    }
}

__global__ void k_scatter(const int* __restrict__ src, const int* __restrict__ dst, int E) {
    int i = blockIdx.x * blockDim.x + threadIdx.x;
    if (i < E) {
        int d = dst[i];
        int pos = g_start[d] + atomicAdd(&g_cursor[d], 1);
        if (pos < CSR_CAP) g_csr[pos] = src[i];
    }
}

// ---------------- per-layer transform: h = feat @ W, s/d attention coeffs ----------------
template <int K, int LAYER>
__global__ void k_transform(const float* __restrict__ feat_in,
                            const float* __restrict__ W,
                            const float* __restrict__ asrc,
                            const float* __restrict__ adst) {
    const int NPB = 8;
    __shared__ float sW[K * 128];
    __shared__ float sA[256];
    __shared__ float sF[NPB * K];
    const float* feat = (LAYER == 1) ? feat_in : g_f1;
    int t = threadIdx.x;  // 128 threads
    for (int i = t; i < K * 128; i += 128) sW[i] = W[i];
    sA[t]       = asrc[t];
    sA[128 + t] = adst[t];
    int nbase = blockIdx.x * NPB;
    for (int i = t; i < NPB * K; i += 128) {
        long idx = (long)nbase * K + i;
        sF[i] = (idx < (long)NN * K) ? feat[idx] : 0.f;
    }
    __syncthreads();
    int lane = t & 31, hd = t >> 5;
    #pragma unroll
    for (int j = 0; j < NPB; j++) {
        int n = nbase + j;
        if (n >= NN) break;
        float acc = 0.f;
        #pragma unroll
        for (int k = 0; k < K; k++) acc = fmaf(sF[j * K + k], sW[k * 128 + t], acc);
        g_h[n * 128 + t] = acc;
        float sv = acc * sA[t];
        float dv = acc * sA[128 + t];
        #pragma unroll
        for (int off = 16; off; off >>= 1) {
            sv += __shfl_xor_sync(FULL, sv, off);
            dv += __shfl_xor_sync(FULL, dv, off);
        }
        if (lane == 0) { g_s[n * 4 + hd] = sv; g_d[n * 4 + hd] = dv; }
    }
}

// ---------------- aggregation (single pass, no max-shift) ----------------
// warp per node. lane l gathers h channels [l*4, l*4+4) -> head = l>>3.
template <int LAYER>
__global__ void k_aggregate(const float* __restrict__ bias) {
    int n = blockIdx.x * (blockDim.x >> 5) + (threadIdx.x >> 5);
    if (n >= NN) return;
    int lane = threadIdx.x & 31;
    int head = lane >> 3;
    int e0 = g_start[n], e1 = g_start[n + 1];
    float dh = g_d[n * 4 + head];

    float ax = 0.f, ay = 0.f, az = 0.f, aw = 0.f;
    float den = 0.f;
    for (int base = e0; base < e1; base += 32) {
        int cnt = min(32, e1 - base);
        int idx = 0;
        if (base + lane < e1) idx = g_csr[base + lane];
        for (int j = 0; j < cnt; j++) {
            int s = __shfl_sync(FULL, idx, j);
            float a = g_s[s * 4 + head] + dh;
            a = a > 0.f ? a : 0.2f * a;
            float w = __expf(a);
            den += w;
            float4 v = *(const float4*)(g_h + s * 128 + lane * 4);
            ax = fmaf(w, v.x, ax);
            ay = fmaf(w, v.y, ay);
            az = fmaf(w, v.z, az);
            aw = fmaf(w, v.w, aw);
        }
    }
    float inv = 0.25f / den;
    ax *= inv; ay *= inv; az *= inv; aw *= inv;
    // sum 4 heads: lanes differing in bits 3,4 hold same channels
    #pragma unroll
    for (int off = 8; off <= 16; off <<= 1) {
        ax += __shfl_xor_sync(FULL, ax, off);
        ay += __shfl_xor_sync(FULL, ay, off);
        az += __shfl_xor_sync(FULL, az, off);
        aw += __shfl_xor_sync(FULL, aw, off);
    }
    if (lane < 8) {
        float4 bv = ((const float4*)bias)[lane];
        float4 o;
        o.x = fmaxf(ax + bv.x, 0.f);
        o.y = fmaxf(ay + bv.y, 0.f);
        o.z = fmaxf(az + bv.z, 0.f);
        o.w = fmaxf(aw + bv.w, 0.f);
        float* dstp = (LAYER == 1) ? g_f1 : g_f2;
        *(float4*)(dstp + n * 32 + lane * 4) = o;
    }
}

// ---------------- node logits ----------------
__global__ void k_node_logits(const float* __restrict__ Wn,
                              const float* __restrict__ bn,
                              float* __restrict__ out) {
    int n = blockIdx.x * blockDim.x + threadIdx.x;
    if (n >= NN) return;
    float o0 = bn[0], o1 = bn[1];
    const float4* fp = (const float4*)(g_f2 + n * 32);
    #pragma unroll
    for (int q = 0; q < 8; q++) {
        float4 v = fp[q];
        int k = q * 4;
        o0 = fmaf(v.x, __ldg(&Wn[k * 2]),       o0);
        o1 = fmaf(v.x, __ldg(&Wn[k * 2 + 1]),   o1);
        o0 = fmaf(v.y, __ldg(&Wn[(k+1) * 2]),   o0);
        o1 = fmaf(v.y, __ldg(&Wn[(k+1) * 2+1]), o1);
        o0 = fmaf(v.z, __ldg(&Wn[(k+2) * 2]),   o0);
        o1 = fmaf(v.z, __ldg(&Wn[(k+2) * 2+1]), o1);
        o0 = fmaf(v.w, __ldg(&Wn[(k+3) * 2]),   o0);
        o1 = fmaf(v.w, __ldg(&Wn[(k+3) * 2+1]), o1);
    }
    out[n * 2]     = o0;
    out[n * 2 + 1] = o1;
}

// ---------------- edge MLP: register-cached weights, grid-stride warps ----------------
__global__ void __launch_bounds__(128, 3)
k_edge_mlp(const int* __restrict__ ea,
           const int* __restrict__ eb, int EL,
           const float* __restrict__ We1,
           const float* __restrict__ be1,
           const float* __restrict__ We2,
           const float* __restrict__ be2,
           float* __restrict__ out) {
    int lane = threadIdx.x & 31;
    // register-cache: lane owns output columns {lane, lane+32}
    float w0[64], w1[64];
    #pragma unroll
    for (int j = 0; j < 64; j++) {
        w0[j] = We1[j * 64 + lane];
        w1[j] = We1[j * 64 + lane + 32];
    }
    float b0 = be1[lane], b1 = be1[lane + 32];
    float v0 = We2[lane], v1 = We2[lane + 32];
    float bb2 = be2[0];

    int nwarps = gridDim.x * (blockDim.x >> 5);
    int w = blockIdx.x * (blockDim.x >> 5) + (threadIdx.x >> 5);
    for (int e = w; e < EL; e += nwarps) {
        int a = ea[e], b = eb[e];
        float xa = g_f2[a * 32 + lane];
        float xb = g_f2[b * 32 + lane];
        float h0 = b0, h1 = b1;
        #pragma unroll
        for (int j = 0; j < 32; j++) {
            float u = __shfl_sync(FULL, xa, j);
            h0 = fmaf(u, w0[j], h0);
            h1 = fmaf(u, w1[j], h1);
        }
        #pragma unroll
        for (int j = 0; j < 32; j++) {
            float u = __shfl_sync(FULL, xb, j);
            h0 = fmaf(u, w0[j + 32], h0);
            h1 = fmaf(u, w1[j + 32], h1);
        }
        h0 = fmaxf(h0, 0.f);
        h1 = fmaxf(h1, 0.f);
        float p = fmaf(h0, v0, h1 * v1);
        #pragma unroll
        for (int off = 16; off; off >>= 1) p += __shfl_xor_sync(FULL, p, off);
        if (lane == 0) out[e] = p + bb2;
    }
}

// ---------------- launch: ONLY kernel launches ----------------
extern "C" void kernel_launch(void* const* d_in, const int* in_sizes, int n_in,
                              void* d_out, int out_size) {
    const float* x    = (const float*)d_in[0];
    const int*   ei   = (const int*)d_in[1];
    const int*   eli  = (const int*)d_in[2];
    const float* W1   = (const float*)d_in[3];
    const float* as1  = (const float*)d_in[4];
    const float* ad1  = (const float*)d_in[5];
    const float* b1   = (const float*)d_in[6];
    const float* W2   = (const float*)d_in[7];
    const float* as2  = (const float*)d_in[8];
    const float* ad2  = (const float*)d_in[9];
    const float* b2   = (const float*)d_in[10];
    const float* Wn   = (const float*)d_in[11];
    const float* bn   = (const float*)d_in[12];
    const float* We1  = (const float*)d_in[13];
    const float* be1  = (const float*)d_in[14];
    const float* We2  = (const float*)d_in[15];
    const float* be2  = (const float*)d_in[16];
    float* out = (float*)d_out;

    int E  = in_sizes[1] / 2;
    int EL = in_sizes[2] / 2;
    const int* src  = ei;
    const int* dst  = ei + E;
    const int* ea   = eli;
    const int* eb   = eli + EL;

    // CSR build
    k_init_deg<<<(NN + 255) / 256, 256>>>();
    k_hist<<<(E + 255) / 256, 256>>>(dst, E);
    k_scan<<<1, 1024>>>(NN);
    k_selfloop<<<(NN + 255) / 256, 256>>>();
    k_scatter<<<(E + 255) / 256, 256>>>(src, dst, E);

    const int TGRID = (NN + 7) / 8;   // 8 nodes per block
    const int AGRID = (NN + 7) / 8;   // 8 warps per block, 1 node per warp

    // layer 1
    k_transform<9, 1><<<TGRID, 128>>>(x, W1, as1, ad1);
    k_aggregate<1><<<AGRID, 256>>>(b1);
    // layer 2
    k_transform<32, 2><<<TGRID, 128>>>(nullptr, W2, as2, ad2);
    k_aggregate<2><<<AGRID, 256>>>(b2);

    // heads
    k_node_logits<<<(NN + 255) / 256, 256>>>(Wn, bn, out);
    int mlp_grid = min(600, (EL + 3) / 4);
    if (mlp_grid < 1) mlp_grid = 1;
    k_edge_mlp<<<mlp_grid, 128>>>(ea, eb, EL, We1, be1, We2, be2, out + NN * 2);
}

// round 5
// speedup vs baseline: 1.7415x; 1.4377x over previous
#include <cuda_runtime.h>
#include <cuda_bf16.h>

#define NN 100000
#define HC 128          // H*C
#define FULL 0xffffffffu
#define CSR_CAP 1900000
#define NB 98           // scan blocks = ceil(NN/1024)

// ---------------- scratch (static __device__, no allocs) ----------------
__device__ float g_h[NN * HC];       // transformed features per layer [N,H,C]
__device__ float g_s[NN * 4];        // src attention coeff per node/head
__device__ float g_d[NN * 4];        // dst attention coeff per node/head
__device__ float g_f1[NN * 32];      // layer-1 output
__device__ float g_f2[NN * 32];      // layer-2 output
__device__ int   g_deg[NN];
__device__ int   g_start[NN + 1];
__device__ int   g_cursor[NN];
__device__ int   g_csr[CSR_CAP];     // src index per (dst-sorted) edge
__device__ int   g_bsum[NB];
__device__ int   g_boff[NB];

// ---------------- CSR build ----------------
__global__ void k_init_deg() {
    int i = blockIdx.x * blockDim.x + threadIdx.x;
    if (i < NN) g_deg[i] = 1;   // self loop
}

__global__ void k_hist(const int* __restrict__ dst, int E) {
    int i = blockIdx.x * blockDim.x + threadIdx.x;
    if (i < E) atomicAdd(&g_deg[dst[i]], 1);
}

// scan phase 1: per-block exclusive scan (1024 threads), block total to g_bsum
__global__ void k_scan1() {
    __shared__ int wsum[32];
    int t = threadIdx.x, lane = t & 31, wid = t >> 5;
    int i = blockIdx.x * 1024 + t;
    int v = (i < NN) ? g_deg[i] : 0;
    int incl = v;
    #pragma unroll
    for (int off = 1; off < 32; off <<= 1) {
        int u = __shfl_up_sync(FULL, incl, off);
        if (lane >= off) incl += u;
    }
    if (lane == 31) wsum[wid] = incl;
    __syncthreads();
    if (wid == 0) {
        int wv = wsum[lane];
        int wincl = wv;
        #pragma unroll
        for (int off = 1; off < 32; off <<= 1) {
            int u = __shfl_up_sync(FULL, wincl, off);
            if (lane >= off) wincl += u;
        }
        wsum[lane] = wincl - wv;   // exclusive warp offsets
    }
    __syncthreads();
    int excl = wsum[wid] + incl - v;
    if (i < NN) g_start[i] = excl;
    if (t == 1023) g_bsum[blockIdx.x] = excl + v;
}

// scan phase 2: single block scans the NB block totals (exclusive)
__global__ void k_scan2() {
    __shared__ int sv[128];
    int t = threadIdx.x;  // 128
    int v = (t < NB) ? g_bsum[t] : 0;
    sv[t] = v;
    __syncthreads();
    // Hillis-Steele inclusive
    for (int off = 1; off < 128; off <<= 1) {
        int u = (t >= off) ? sv[t - off] : 0;
        __syncthreads();
        sv[t] += u;
        __syncthreads();
    }
    if (t < NB) g_boff[t] = sv[t] - v;     // exclusive
    if (t == NB - 1) g_start[NN] = sv[t];  // grand total
}

// scan phase 3 + self-loop: add block offsets, init cursor, write self-loop edge
__global__ void k_scan3_selfloop() {
    int i = blockIdx.x * blockDim.x + threadIdx.x;
    if (i < NN) {
        int p = g_start[i] + g_boff[i >> 10];
        g_start[i] = p;
        g_cursor[i] = 1;
        if (p < CSR_CAP) g_csr[p] = i;
    }
}

__global__ void k_scatter(const int* __restrict__ src, const int* __restrict__ dst, int E) {
    int i = blockIdx.x * blockDim.x + threadIdx.x;
    if (i < E) {
        int d = dst[i];
        int pos = g_start[d] + atomicAdd(&g_cursor[d], 1);
        if (pos < CSR_CAP) g_csr[pos] = src[i];
    }
}

// ---------------- per-layer transform: h = feat @ W, s/d attention coeffs ----------------
template <int K, int LAYER>
__global__ void k_transform(const float* __restrict__ feat_in,
                            const float* __restrict__ W,
                            const float* __restrict__ asrc,
                            const float* __restrict__ adst) {
    const int NPB = 16;
    __shared__ float sW[K * 128];
    __shared__ float sA[256];
    __shared__ float sF[NPB * K];
    const float* feat = (LAYER == 1) ? feat_in : g_f1;
    int t = threadIdx.x;  // 128 threads
    for (int i = t; i < K * 128; i += 128) sW[i] = W[i];
    sA[t]       = asrc[t];
    sA[128 + t] = adst[t];
    int nbase = blockIdx.x * NPB;
    for (int i = t; i < NPB * K; i += 128) {
        long idx = (long)nbase * K + i;
        sF[i] = (idx < (long)NN * K) ? feat[idx] : 0.f;
    }
    __syncthreads();
    int lane = t & 31, hd = t >> 5;
    #pragma unroll
    for (int j = 0; j < NPB; j++) {
        int n = nbase + j;
        if (n >= NN) break;
        float acc = 0.f;
        #pragma unroll
        for (int k = 0; k < K; k++) acc = fmaf(sF[j * K + k], sW[k * 128 + t], acc);
        g_h[n * 128 + t] = acc;
        float sv = acc * sA[t];
        float dv = acc * sA[128 + t];
        #pragma unroll
        for (int off = 16; off; off >>= 1) {
            sv += __shfl_xor_sync(FULL, sv, off);
            dv += __shfl_xor_sync(FULL, dv, off);
        }
        if (lane == 0) { g_s[n * 4 + hd] = sv; g_d[n * 4 + hd] = dv; }
    }
}

// ---------------- aggregation (single pass, no max-shift), unroll x2 ----------------
template <int LAYER>
__global__ void k_aggregate(const float* __restrict__ bias) {
    int n = blockIdx.x * (blockDim.x >> 5) + (threadIdx.x >> 5);
    if (n >= NN) return;
    int lane = threadIdx.x & 31;
    int head = lane >> 3;
    int e0 = g_start[n], e1 = g_start[n + 1];
    float dh = g_d[n * 4 + head];

    float ax = 0.f, ay = 0.f, az = 0.f, aw = 0.f;
    float den = 0.f;
    for (int base = e0; base < e1; base += 32) {
        int cnt = min(32, e1 - base);
        int idx = 0;
        if (base + lane < e1) idx = g_csr[base + lane];
        int j = 0;
        for (; j + 1 < cnt; j += 2) {
            int s0 = __shfl_sync(FULL, idx, j);
            int s1 = __shfl_sync(FULL, idx, j + 1);
            float a0 = g_s[s0 * 4 + head] + dh;
            float a1 = g_s[s1 * 4 + head] + dh;
            a0 = a0 > 0.f ? a0 : 0.2f * a0;
            a1 = a1 > 0.f ? a1 : 0.2f * a1;
            float w0 = __expf(a0), w1 = __expf(a1);
            den += w0 + w1;
            float4 v0 = *(const float4*)(g_h + s0 * 128 + lane * 4);
            float4 v1 = *(const float4*)(g_h + s1 * 128 + lane * 4);
            ax = fmaf(w0, v0.x, ax); ay = fmaf(w0, v0.y, ay);
            az = fmaf(w0, v0.z, az); aw = fmaf(w0, v0.w, aw);
            ax = fmaf(w1, v1.x, ax); ay = fmaf(w1, v1.y, ay);
            az = fmaf(w1, v1.z, az); aw = fmaf(w1, v1.w, aw);
        }
        if (j < cnt) {
            int s = __shfl_sync(FULL, idx, j);
            float a = g_s[s * 4 + head] + dh;
            a = a > 0.f ? a : 0.2f * a;
            float w = __expf(a);
            den += w;
            float4 v = *(const float4*)(g_h + s * 128 + lane * 4);
            ax = fmaf(w, v.x, ax); ay = fmaf(w, v.y, ay);
            az = fmaf(w, v.z, az); aw = fmaf(w, v.w, aw);
        }
    }
    float inv = 0.25f / den;
    ax *= inv; ay *= inv; az *= inv; aw *= inv;
    // sum 4 heads: lanes differing in bits 3,4 hold same channels
    #pragma unroll
    for (int off = 8; off <= 16; off <<= 1) {
        ax += __shfl_xor_sync(FULL, ax, off);
        ay += __shfl_xor_sync(FULL, ay, off);
        az += __shfl_xor_sync(FULL, az, off);
        aw += __shfl_xor_sync(FULL, aw, off);
    }
    if (lane < 8) {
        float4 bv = ((const float4*)bias)[lane];
        float4 o;
        o.x = fmaxf(ax + bv.x, 0.f);
        o.y = fmaxf(ay + bv.y, 0.f);
        o.z = fmaxf(az + bv.z, 0.f);
        o.w = fmaxf(aw + bv.w, 0.f);
        float* dstp = (LAYER == 1) ? g_f1 : g_f2;
        *(float4*)(dstp + n * 32 + lane * 4) = o;
    }
}

// ---------------- node logits ----------------
__global__ void k_node_logits(const float* __restrict__ Wn,
                              const float* __restrict__ bn,
                              float* __restrict__ out) {
    int n = blockIdx.x * blockDim.x + threadIdx.x;
    if (n >= NN) return;
    float o0 = bn[0], o1 = bn[1];
    const float4* fp = (const float4*)(g_f2 + n * 32);
    #pragma unroll
    for (int q = 0; q < 8; q++) {
        float4 v = fp[q];
        int k = q * 4;
        o0 = fmaf(v.x, __ldg(&Wn[k * 2]),       o0);
        o1 = fmaf(v.x, __ldg(&Wn[k * 2 + 1]),   o1);
        o0 = fmaf(v.y, __ldg(&Wn[(k+1) * 2]),   o0);
        o1 = fmaf(v.y, __ldg(&Wn[(k+1) * 2+1]), o1);
        o0 = fmaf(v.z, __ldg(&Wn[(k+2) * 2]),   o0);
        o1 = fmaf(v.z, __ldg(&Wn[(k+2) * 2+1]), o1);
        o0 = fmaf(v.w, __ldg(&Wn[(k+3) * 2]),   o0);
        o1 = fmaf(v.w, __ldg(&Wn[(k+3) * 2+1]), o1);
    }
    out[n * 2]     = o0;
    out[n * 2 + 1] = o1;
}

// ---------------- edge MLP: register-cached weights, grid-stride warps ----------------
__global__ void __launch_bounds__(128, 3)
k_edge_mlp(const int* __restrict__ ea,
           const int* __restrict__ eb, int EL,
           const float* __restrict__ We1,
           const float* __restrict__ be1,
           const float* __restrict__ We2,
           const float* __restrict__ be2,
           float* __restrict__ out) {
    int lane = threadIdx.x & 31;
    // register-cache: lane owns output columns {lane, lane+32}
    float w0[64], w1[64];
    #pragma unroll
    for (int j = 0; j < 64; j++) {
        w0[j] = We1[j * 64 + lane];
        w1[j] = We1[j * 64 + lane + 32];
    }
    float b0 = be1[lane], b1 = be1[lane + 32];
    float v0 = We2[lane], v1 = We2[lane + 32];
    float bb2 = be2[0];

    int nwarps = gridDim.x * (blockDim.x >> 5);
    int w = blockIdx.x * (blockDim.x >> 5) + (threadIdx.x >> 5);
    for (int e = w; e < EL; e += nwarps) {
        int a = ea[e], b = eb[e];
        float xa = g_f2[a * 32 + lane];
        float xb = g_f2[b * 32 + lane];
        float h0 = b0, h1 = b1;
        #pragma unroll
        for (int j = 0; j < 32; j++) {
            float u = __shfl_sync(FULL, xa, j);
            h0 = fmaf(u, w0[j], h0);
            h1 = fmaf(u, w1[j], h1);
        }
        #pragma unroll
        for (int j = 0; j < 32; j++) {
            float u = __shfl_sync(FULL, xb, j);
            h0 = fmaf(u, w0[j + 32], h0);
            h1 = fmaf(u, w1[j + 32], h1);
        }
        h0 = fmaxf(h0, 0.f);
        h1 = fmaxf(h1, 0.f);
        float p = fmaf(h0, v0, h1 * v1);
        #pragma unroll
        for (int off = 16; off; off >>= 1) p += __shfl_xor_sync(FULL, p, off);
        if (lane == 0) out[e] = p + bb2;
    }
}

// ---------------- launch: ONLY kernel launches ----------------
extern "C" void kernel_launch(void* const* d_in, const int* in_sizes, int n_in,
                              void* d_out, int out_size) {
    const float* x    = (const float*)d_in[0];
    const int*   ei   = (const int*)d_in[1];
    const int*   eli  = (const int*)d_in[2];
    const float* W1   = (const float*)d_in[3];
    const float* as1  = (const float*)d_in[4];
    const float* ad1  = (const float*)d_in[5];
    const float* b1   = (const float*)d_in[6];
    const float* W2   = (const float*)d_in[7];
    const float* as2  = (const float*)d_in[8];
    const float* ad2  = (const float*)d_in[9];
    const float* b2   = (const float*)d_in[10];
    const float* Wn   = (const float*)d_in[11];
    const float* bn   = (const float*)d_in[12];
    const float* We1  = (const float*)d_in[13];
    const float* be1  = (const float*)d_in[14];
    const float* We2  = (const float*)d_in[15];
    const float* be2  = (const float*)d_in[16];
    float* out = (float*)d_out;

    int E  = in_sizes[1] / 2;
    int EL = in_sizes[2] / 2;
    const int* src  = ei;
    const int* dst  = ei + E;
    const int* ea   = eli;
    const int* eb   = eli + EL;

    // CSR build (parallel scan)
    k_init_deg<<<(NN + 255) / 256, 256>>>();
    k_hist<<<(E + 255) / 256, 256>>>(dst, E);
    k_scan1<<<NB, 1024>>>();
    k_scan2<<<1, 128>>>();
    k_scan3_selfloop<<<(NN + 255) / 256, 256>>>();
    k_scatter<<<(E + 255) / 256, 256>>>(src, dst, E);

    const int TGRID = (NN + 15) / 16;  // 16 nodes per block
    const int AGRID = (NN + 7) / 8;    // 8 warps per block, 1 node per warp

    // layer 1
    k_transform<9, 1><<<TGRID, 128>>>(x, W1, as1, ad1);
    k_aggregate<1><<<AGRID, 256>>>(b1);
    // layer 2
    k_transform<32, 2><<<TGRID, 128>>>(nullptr, W2, as2, ad2);
    k_aggregate<2><<<AGRID, 256>>>(b2);

    // heads
    k_node_logits<<<(NN + 255) / 256, 256>>>(Wn, bn, out);
    // 3 blocks/SM residency * 148 SMs = 444 -> exactly one wave
    k_edge_mlp<<<444, 128>>>(ea, eb, EL, We1, be1, We2, be2, out + NN * 2);
}

// round 7
// speedup vs baseline: 2.8190x; 1.6187x over previous
#include <cuda_runtime.h>
#include <cuda_fp16.h>
#include <cuda_bf16.h>
#include <cstdint>

#define NN 100000
#define FULL 0xffffffffu
#define CSR_CAP 1900000
#define NB 98           // scan blocks = ceil(NN/1024)

// ---------------- scratch (static __device__, no allocs) ----------------
__device__ __half2 g_h2[NN * 64];    // transformed features [N,128ch] as half2
__device__ float g_s[NN * 4];        // src attention coeff per node/head
__device__ float g_d[NN * 4];        // dst attention coeff per node/head
__device__ float g_f1[NN * 32];      // layer-1 output
__device__ float g_f2[NN * 32];      // layer-2 output
__device__ int   g_deg[NN];
__device__ int   g_start[NN + 1];
__device__ int   g_cursor[NN];
__device__ int   g_csr[CSR_CAP];     // src index per (dst-sorted) edge
__device__ int   g_bsum[NB];
__device__ int   g_boff[NB];

// ---------------- CSR build ----------------
__global__ void k_init_deg() {
    int i = blockIdx.x * blockDim.x + threadIdx.x;
    if (i < NN) g_deg[i] = 1;   // self loop
}

__global__ void k_hist(const int* __restrict__ dst, int E) {
    int i = blockIdx.x * blockDim.x + threadIdx.x;
    if (i < E) atomicAdd(&g_deg[dst[i]], 1);
}

__global__ void k_scan1() {
    __shared__ int wsum[32];
    int t = threadIdx.x, lane = t & 31, wid = t >> 5;
    int i = blockIdx.x * 1024 + t;
    int v = (i < NN) ? g_deg[i] : 0;
    int incl = v;
    #pragma unroll
    for (int off = 1; off < 32; off <<= 1) {
        int u = __shfl_up_sync(FULL, incl, off);
        if (lane >= off) incl += u;
    }
    if (lane == 31) wsum[wid] = incl;
    __syncthreads();
    if (wid == 0) {
        int wv = wsum[lane];
        int wincl = wv;
        #pragma unroll
        for (int off = 1; off < 32; off <<= 1) {
            int u = __shfl_up_sync(FULL, wincl, off);
            if (lane >= off) wincl += u;
        }
        wsum[lane] = wincl - wv;
    }
    __syncthreads();
    int excl = wsum[wid] + incl - v;
    if (i < NN) g_start[i] = excl;
    if (t == 1023) g_bsum[blockIdx.x] = excl + v;
}

__global__ void k_scan2() {
    __shared__ int sv[128];
    int t = threadIdx.x;  // 128
    int v = (t < NB) ? g_bsum[t] : 0;
    sv[t] = v;
    __syncthreads();
    for (int off = 1; off < 128; off <<= 1) {
        int u = (t >= off) ? sv[t - off] : 0;
        __syncthreads();
        sv[t] += u;
        __syncthreads();
    }
    if (t < NB) g_boff[t] = sv[t] - v;
    if (t == NB - 1) g_start[NN] = sv[t];
}

__global__ void k_scan3_selfloop() {
    int i = blockIdx.x * blockDim.x + threadIdx.x;
    if (i < NN) {
        int p = g_start[i] + g_boff[i >> 10];
        g_start[i] = p;
        g_cursor[i] = 1;
        if (p < CSR_CAP) g_csr[p] = i;
    }
}

__global__ void k_scatter(const int* __restrict__ src, const int* __restrict__ dst, int E) {
    int i = blockIdx.x * blockDim.x + threadIdx.x;
    if (i < E) {
        int d = dst[i];
        int pos = g_start[d] + atomicAdd(&g_cursor[d], 1);
        if (pos < CSR_CAP) g_csr[pos] = src[i];
    }
}

// ---------------- transform: h = feat @ W (fp32 math, fp16 store), s/d coeffs fp32 ----------------
template <int K, int LAYER>
__global__ void k_transform(const float* __restrict__ feat_in,
                            const float* __restrict__ W,
                            const float* __restrict__ asrc,
                            const float* __restrict__ adst) {
    const int NPB = 16;
    __shared__ float sW[K * 128];
    __shared__ float sA[256];
    __shared__ float sF[NPB * K];
    const float* feat = (LAYER == 1) ? feat_in : g_f1;
    int t = threadIdx.x;  // 128 threads
    for (int i = t; i < K * 128; i += 128) sW[i] = W[i];
    sA[t]       = asrc[t];
    sA[128 + t] = adst[t];
    int nbase = blockIdx.x * NPB;
    for (int i = t; i < NPB * K; i += 128) {
        long idx = (long)nbase * K + i;
        sF[i] = (idx < (long)NN * K) ? feat[idx] : 0.f;
    }
    __syncthreads();
    int lane = t & 31, hd = t >> 5;
    #pragma unroll
    for (int j = 0; j < NPB; j++) {
        int n = nbase + j;
        if (n >= NN) break;
        float acc = 0.f;
        #pragma unroll
        for (int k = 0; k < K; k++) acc = fmaf(sF[j * K + k], sW[k * 128 + t], acc);
        // pack pairs of channels into half2 (even thread stores t, t+1)
        float hi = __shfl_xor_sync(FULL, acc, 1);
        if ((t & 1) == 0) g_h2[n * 64 + (t >> 1)] = __floats2half2_rn(acc, hi);
        float sv = acc * sA[t];
        float dv = acc * sA[128 + t];
        #pragma unroll
        for (int off = 16; off; off >>= 1) {
            sv += __shfl_xor_sync(FULL, sv, off);
            dv += __shfl_xor_sync(FULL, dv, off);
        }
        if (lane == 0) { g_s[n * 4 + hd] = sv; g_d[n * 4 + hd] = dv; }
    }
}

// ---------------- aggregation: single-pass softmax, fp16 gathers, unroll x2 ----------------
template <int LAYER>
__global__ void k_aggregate(const float* __restrict__ bias) {
    int n = blockIdx.x * (blockDim.x >> 5) + (threadIdx.x >> 5);
    if (n >= NN) return;
    int lane = threadIdx.x & 31;
    int head = lane >> 3;
    int e0 = g_start[n], e1 = g_start[n + 1];
    float dh = g_d[n * 4 + head];

    float ax = 0.f, ay = 0.f, az = 0.f, aw = 0.f;
    float den = 0.f;
    for (int base = e0; base < e1; base += 32) {
        int cnt = min(32, e1 - base);
        int idx = 0;
        if (base + lane < e1) idx = g_csr[base + lane];
        int j = 0;
        for (; j + 1 < cnt; j += 2) {
            int s0 = __shfl_sync(FULL, idx, j);
            int s1 = __shfl_sync(FULL, idx, j + 1);
            float a0 = g_s[s0 * 4 + head] + dh;
            float a1 = g_s[s1 * 4 + head] + dh;
            a0 = a0 > 0.f ? a0 : 0.2f * a0;
            a1 = a1 > 0.f ? a1 : 0.2f * a1;
            float w0 = __expf(a0), w1 = __expf(a1);
            den += w0 + w1;
            uint2 u0 = *(const uint2*)(g_h2 + (size_t)s0 * 64 + lane * 2);
            uint2 u1 = *(const uint2*)(g_h2 + (size_t)s1 * 64 + lane * 2);
            float2 p0 = __half22float2(*(__half2*)&u0.x);
            float2 q0 = __half22float2(*(__half2*)&u0.y);
            float2 p1 = __half22float2(*(__half2*)&u1.x);
            float2 q1 = __half22float2(*(__half2*)&u1.y);
            ax = fmaf(w0, p0.x, ax); ay = fmaf(w0, p0.y, ay);
            az = fmaf(w0, q0.x, az); aw = fmaf(w0, q0.y, aw);
            ax = fmaf(w1, p1.x, ax); ay = fmaf(w1, p1.y, ay);
            az = fmaf(w1, q1.x, az); aw = fmaf(w1, q1.y, aw);
        }
        if (j < cnt) {
            int s = __shfl_sync(FULL, idx, j);
            float a = g_s[s * 4 + head] + dh;
            a = a > 0.f ? a : 0.2f * a;
            float w = __expf(a);
            den += w;
            uint2 u = *(const uint2*)(g_h2 + (size_t)s * 64 + lane * 2);
            float2 p = __half22float2(*(__half2*)&u.x);
            float2 q = __half22float2(*(__half2*)&u.y);
            ax = fmaf(w, p.x, ax); ay = fmaf(w, p.y, ay);
            az = fmaf(w, q.x, az); aw = fmaf(w, q.y, aw);
        }
    }
    float inv = 0.25f / den;
    ax *= inv; ay *= inv; az *= inv; aw *= inv;
    #pragma unroll
    for (int off = 8; off <= 16; off <<= 1) {
        ax += __shfl_xor_sync(FULL, ax, off);
        ay += __shfl_xor_sync(FULL, ay, off);
        az += __shfl_xor_sync(FULL, az, off);
        aw += __shfl_xor_sync(FULL, aw, off);
    }
    if (lane < 8) {
        float4 bv = ((const float4*)bias)[lane];
        float4 o;
        o.x = fmaxf(ax + bv.x, 0.f);
        o.y = fmaxf(ay + bv.y, 0.f);
        o.z = fmaxf(az + bv.z, 0.f);
        o.w = fmaxf(aw + bv.w, 0.f);
        float* dstp = (LAYER == 1) ? g_f1 : g_f2;
        *(float4*)(dstp + n * 32 + lane * 4) = o;
    }
}

// ---------------- node logits ----------------
__global__ void k_node_logits(const float* __restrict__ Wn,
                              const float* __restrict__ bn,
                              float* __restrict__ out) {
    int n = blockIdx.x * blockDim.x + threadIdx.x;
    if (n >= NN) return;
    float o0 = bn[0], o1 = bn[1];
    const float4* fp = (const float4*)(g_f2 + n * 32);
    #pragma unroll
    for (int q = 0; q < 8; q++) {
        float4 v = fp[q];
        int k = q * 4;
        o0 = fmaf(v.x, __ldg(&Wn[k * 2]),       o0);
        o1 = fmaf(v.x, __ldg(&Wn[k * 2 + 1]),   o1);
        o0 = fmaf(v.y, __ldg(&Wn[(k+1) * 2]),   o0);
        o1 = fmaf(v.y, __ldg(&Wn[(k+1) * 2+1]), o1);
        o0 = fmaf(v.z, __ldg(&Wn[(k+2) * 2]),   o0);
        o1 = fmaf(v.z, __ldg(&Wn[(k+2) * 2+1]), o1);
        o0 = fmaf(v.w, __ldg(&Wn[(k+3) * 2]),   o0);
        o1 = fmaf(v.w, __ldg(&Wn[(k+3) * 2+1]), o1);
    }
    out[n * 2]     = o0;
    out[n * 2 + 1] = o1;
}

// ---------------- edge MLP via mma.sync m16n8k8 TF32 ----------------
// warp tile = 16 edges. H[16,64] = X[16,64] @ We1[64,64]; out = relu(H+b1) @ We2 + b2.
__device__ __forceinline__ unsigned int f2tf32(float f) {
    unsigned int u;
    asm("cvt.rna.tf32.f32 %0, %1;" : "=r"(u) : "f"(f));
    return u;
}

#define SW_STRIDE 72

__global__ void k_edge_mlp_mma(const int* __restrict__ ea,
                               const int* __restrict__ eb, int EL,
                               const float* __restrict__ We1,
                               const float* __restrict__ be1,
                               const float* __restrict__ We2,
                               const float* __restrict__ be2,
                               float* __restrict__ out) {
    __shared__ unsigned int sW[64 * SW_STRIDE];   // We1 as tf32 bits, [k][n] padded
    __shared__ float sB[64];                      // be1
    __shared__ float sV[64];                      // We2
    int t = threadIdx.x;  // 128
    for (int i = t; i < 64 * 64; i += 128) {
        int k = i >> 6, n = i & 63;
        sW[k * SW_STRIDE + n] = f2tf32(We1[i]);
    }
    if (t < 64) { sB[t] = be1[t]; sV[t] = We2[t]; }
    float bb2 = be2[0];
    __syncthreads();

    int lane = t & 31;
    int g = lane >> 2;       // 0..7
    int tg = lane & 3;       // 0..3
    int ntiles = (EL + 15) >> 4;
    int nwarps = gridDim.x * (blockDim.x >> 5);
    int w = blockIdx.x * (blockDim.x >> 5) + (t >> 5);

    for (int tile = w; tile < ntiles; tile += nwarps) {
        int e0 = tile << 4;
        // load 16 edge index pairs (lanes 0..15)
        int ra = 0, rb = 0;
        if (lane < 16) {
            int e = e0 + lane;
            if (e < EL) { ra = ea[e]; rb = eb[e]; }
        }
        int iaG  = __shfl_sync(FULL, ra, g);
        int iaG8 = __shfl_sync(FULL, ra, g + 8);
        int ibG  = __shfl_sync(FULL, rb, g);
        int ibG8 = __shfl_sync(FULL, rb, g + 8);
        const float* pA0 = g_f2 + (size_t)iaG  * 32;  // row g,   cols 0..31
        const float* pA1 = g_f2 + (size_t)iaG8 * 32;  // row g+8, cols 0..31
        const float* pB0 = g_f2 + (size_t)ibG  * 32;  // row g,   cols 32..63
        const float* pB1 = g_f2 + (size_t)ibG8 * 32;  // row g+8, cols 32..63

        // A fragments for 8 k-chunks
        unsigned int A0[8], A1[8], A2[8], A3[8];
        #pragma unroll
        for (int kc = 0; kc < 4; kc++) {
            int c = kc * 8 + tg;
            A0[kc] = f2tf32(pA0[c]);
            A1[kc] = f2tf32(pA1[c]);
            A2[kc] = f2tf32(pA0[c + 4]);
            A3[kc] = f2tf32(pA1[c + 4]);
        }
        #pragma unroll
        for (int kc = 4; kc < 8; kc++) {
            int c = (kc - 4) * 8 + tg;
            A0[kc] = f2tf32(pB0[c]);
            A1[kc] = f2tf32(pB1[c]);
            A2[kc] = f2tf32(pB0[c + 4]);
            A3[kc] = f2tf32(pB1[c + 4]);
        }

        float pg = 0.f, pg8 = 0.f;
        #pragma unroll
        for (int nc = 0; nc < 8; nc++) {
            float c0 = 0.f, c1 = 0.f, c2 = 0.f, c3 = 0.f;
            int n0 = nc * 8 + g;
            #pragma unroll
            for (int kc = 0; kc < 8; kc++) {
                unsigned int b0 = sW[(kc * 8 + tg) * SW_STRIDE + n0];
                unsigned int b1 = sW[(kc * 8 + tg + 4) * SW_STRIDE + n0];
                asm volatile(
                    "mma.sync.aligned.m16n8k8.row.col.f32.tf32.tf32.f32 "
                    "{%0,%1,%2,%3},{%4,%5,%6,%7},{%8,%9},{%0,%1,%2,%3};"
                    : "+f"(c0), "+f"(c1), "+f"(c2), "+f"(c3)
                    : "r"(A0[kc]), "r"(A1[kc]), "r"(A2[kc]), "r"(A3[kc]),
                      "r"(b0), "r"(b1));
            }
            int col0 = nc * 8 + 2 * tg;
            float bi0 = sB[col0], bi1 = sB[col0 + 1];
            float v0 = sV[col0],  v1 = sV[col0 + 1];
            pg  = fmaf(fmaxf(c0 + bi0, 0.f), v0, pg);
            pg  = fmaf(fmaxf(c1 + bi1, 0.f), v1, pg);
            pg8 = fmaf(fmaxf(c2 + bi0, 0.f), v0, pg8);
            pg8 = fmaf(fmaxf(c3 + bi1, 0.f), v1, pg8);
        }
        // reduce over tg (4-lane groups)
        pg  += __shfl_xor_sync(FULL, pg, 1);
        pg  += __shfl_xor_sync(FULL, pg, 2);
        pg8 += __shfl_xor_sync(FULL, pg8, 1);
        pg8 += __shfl_xor_sync(FULL, pg8, 2);
        if (tg == 0) {
            if (e0 + g < EL)     out[e0 + g]     = pg + bb2;
            if (e0 + g + 8 < EL) out[e0 + g + 8] = pg8 + bb2;
        }
    }
}

// ---------------- launch: ONLY kernel launches ----------------
extern "C" void kernel_launch(void* const* d_in, const int* in_sizes, int n_in,
                              void* d_out, int out_size) {
    const float* x    = (const float*)d_in[0];
    const int*   ei   = (const int*)d_in[1];
    const int*   eli  = (const int*)d_in[2];
    const float* W1   = (const float*)d_in[3];
    const float* as1  = (const float*)d_in[4];
    const float* ad1  = (const float*)d_in[5];
    const float* b1   = (const float*)d_in[6];
    const float* W2   = (const float*)d_in[7];
    const float* as2  = (const float*)d_in[8];
    const float* ad2  = (const float*)d_in[9];
    const float* b2   = (const float*)d_in[10];
    const float* Wn   = (const float*)d_in[11];
    const float* bn   = (const float*)d_in[12];
    const float* We1  = (const float*)d_in[13];
    const float* be1  = (const float*)d_in[14];
    const float* We2  = (const float*)d_in[15];
    const float* be2  = (const float*)d_in[16];
    float* out = (float*)d_out;

    int E  = in_sizes[1] / 2;
    int EL = in_sizes[2] / 2;
    const int* src  = ei;
    const int* dst  = ei + E;
    const int* ea   = eli;
    const int* eb   = eli + EL;

    // CSR build (parallel scan)
    k_init_deg<<<(NN + 255) / 256, 256>>>();
    k_hist<<<(E + 255) / 256, 256>>>(dst, E);
    k_scan1<<<NB, 1024>>>();
    k_scan2<<<1, 128>>>();
    k_scan3_selfloop<<<(NN + 255) / 256, 256>>>();
    k_scatter<<<(E + 255) / 256, 256>>>(src, dst, E);

    const int TGRID = (NN + 15) / 16;  // 16 nodes per block
    const int AGRID = (NN + 7) / 8;    // 8 warps per block, 1 node per warp

    // layer 1
    k_transform<9, 1><<<TGRID, 128>>>(x, W1, as1, ad1);
    k_aggregate<1><<<AGRID, 256>>>(b1);
    // layer 2
    k_transform<32, 2><<<TGRID, 128>>>(nullptr, W2, as2, ad2);
    k_aggregate<2><<<AGRID, 256>>>(b2);

    // heads
    k_node_logits<<<(NN + 255) / 256, 256>>>(Wn, bn, out);
    k_edge_mlp_mma<<<592, 128>>>(ea, eb, EL, We1, be1, We2, be2, out + NN * 2);
}